// round 10
// baseline (speedup 1.0000x reference)
#include <cuda_runtime.h>
#include <math.h>

#define Nn 32768
#define Ee 262144
#define HASHN (1u<<20)

// ---------------- static device scratch ----------------
__device__ double g_a[Nn], g_b[Nn];
__device__ double g_rawex[Ee];
__device__ unsigned long long g_mx[Nn];
__device__ double g_sum[Nn];
__device__ float  g_score[Ee];
__device__ unsigned long long g_key[Ee];
__device__ unsigned long long g_best[Nn];
__device__ int    g_matched[Nn], g_cluster[Nn], g_partner[Nn];
__device__ float  g_nscore[Nn];
__device__ int    g_frontA[Ee], g_frontB[Ee];
__device__ int    g_fcnt, g_P, g_uc, g_e64;
__device__ unsigned int g_hash[HASHN];
__device__ int    g_us[Ee], g_ud[Ee];
__device__ float  g_logit[Ee*4], g_exv[Ee*4];
__device__ unsigned int g_mx4[Nn*4];
__device__ float  g_sum4[Nn*4];
__device__ double g_lnsum, g_lnsq, g_mean, g_inv;
__device__ float  g_xp[(size_t)Nn*256];
__device__ float  g_xl[(size_t)Nn*256];
__device__ float  g_xr[(size_t)Nn*256];
__device__ float  g_h [(size_t)Nn*256];

// ---------------- edge accessors (dtype-agnostic) ----------------
static __device__ __forceinline__ int esrc(const void* ei, int e){
    return g_e64 ? (int)((const long long*)ei)[e] : ((const int*)ei)[e];
}
static __device__ __forceinline__ int edst(const void* ei, int e){
    return g_e64 ? (int)((const long long*)ei)[Ee + e] : ((const int*)ei)[Ee + e];
}

// ---------------- order-preserving encodings ----------------
static __device__ __forceinline__ unsigned long long encd(double x){
    unsigned long long b = (unsigned long long)__double_as_longlong(x);
    return (b & 0x8000000000000000ULL) ? ~b : (b | 0x8000000000000000ULL);
}
static __device__ __forceinline__ double decd(unsigned long long u){
    unsigned long long b = (u & 0x8000000000000000ULL) ? (u ^ 0x8000000000000000ULL) : ~u;
    return __longlong_as_double((long long)b);
}
static __device__ __forceinline__ unsigned int encf(float x){
    unsigned int b = __float_as_uint(x);
    return (b & 0x80000000u) ? ~b : (b | 0x80000000u);
}
static __device__ __forceinline__ float decf(unsigned int u){
    unsigned int b = (u & 0x80000000u) ? (u ^ 0x80000000u) : ~u;
    return __uint_as_float(b);
}

// ---------------- dtype detect + init ----------------
__global__ void k_detect(const void* ei){
    const long long* p = (const long long*)ei;
    int ok = 1;
    for (int i = 0; i < 16; i++){
        long long v = p[i];
        if (v < 0 || v >= Nn) { ok = 0; break; }
    }
    g_e64 = ok;
}

__global__ void k_init(){
    int i = blockIdx.x*blockDim.x + threadIdx.x;
    if (i < (int)HASHN) g_hash[i] = 0xFFFFFFFFu;
    if (i < Nn){
        g_mx[i]=0ULL; g_sum[i]=0.0; g_best[i]=0ULL;
        g_matched[i]=0; g_cluster[i]=i; g_partner[i]=-1; g_nscore[i]=1.0f;
    }
    if (i == 0){ g_P=0; g_uc=0; g_fcnt=0; }
}
__global__ void k_lnzero(){ g_lnsum = 0.0; g_lnsq = 0.0; }

// ---------------- edge scores ----------------
__global__ __launch_bounds__(256) void k_pool(const float* __restrict__ x, const float* __restrict__ pw){
    int gt = blockIdx.x*blockDim.x + threadIdx.x;
    int w = gt >> 5, lane = gt & 31;
    if (w >= Nn) return;
    double sa=0.0, sb=0.0;
    #pragma unroll
    for (int k=0;k<8;k++){
        int c = lane + 32*k;
        double xv = (double)x[(size_t)w*256 + c];
        sa += xv * (double)__ldg(&pw[c]);
        sb += xv * (double)__ldg(&pw[256 + c]);
    }
    #pragma unroll
    for (int o=16;o;o>>=1){
        sa += __shfl_down_sync(0xffffffffu, sa, o);
        sb += __shfl_down_sync(0xffffffffu, sb, o);
    }
    if (lane==0){ g_a[w]=sa; g_b[w]=sb; }
}

__global__ void k_raw(const void* __restrict__ ei, const float* __restrict__ pb){
    int e = blockIdx.x*blockDim.x + threadIdx.x;
    if (e >= Ee) return;
    int s = esrc(ei,e), d = edst(ei,e);
    double r = g_a[s] + g_b[d] + (double)pb[0];
    g_rawex[e] = r;
    atomicMax(&g_mx[d], encd(r));
}

__global__ void k_ex(const void* __restrict__ ei){
    int e = blockIdx.x*blockDim.x + threadIdx.x;
    if (e >= Ee) return;
    int d = edst(ei,e);
    double ex = exp(g_rawex[e] - decd(g_mx[d]));
    g_rawex[e] = ex;
    atomicAdd(&g_sum[d], ex);
}

__global__ void k_scorekey(const void* __restrict__ ei){
    int e = blockIdx.x*blockDim.x + threadIdx.x;
    if (e >= Ee) return;
    int d = edst(ei,e);
    float fs = (float)(g_rawex[e]/g_sum[d] + 0.5);
    g_score[e] = fs;
    unsigned int ub = __float_as_uint(fs) | 0x80000000u;   // fs > 0 always
    g_key[e] = ((unsigned long long)ub << 32) | (unsigned long long)(0xFFFFFFFFu - (unsigned)e);
}

// ---------------- matching (locally-dominant == sequential greedy) ----------------
static __device__ __forceinline__ void do_match(int e, int s, int d){
    int rep = s<d ? s : d;
    int oth = s<d ? d : s;
    g_matched[s]=1; g_matched[d]=1;
    g_cluster[oth]=rep;
    g_partner[rep]=oth;
    g_nscore[rep]=g_score[e];
    atomicAdd(&g_P, 1);
}

__global__ void k_max1(const void* __restrict__ ei){
    int e = blockIdx.x*blockDim.x + threadIdx.x;
    if (e >= Ee) return;
    unsigned long long k = g_key[e];
    atomicMax(&g_best[esrc(ei,e)], k);
    atomicMax(&g_best[edst(ei,e)], k);
}
__global__ void k_match1(const void* __restrict__ ei){
    int e = blockIdx.x*blockDim.x + threadIdx.x;
    if (e >= Ee) return;
    int s = esrc(ei,e), d = edst(ei,e);
    unsigned long long k = g_key[e];
    if (g_best[s]==k && g_best[d]==k) do_match(e,s,d);
}
__global__ void k_compact1(const void* __restrict__ ei){
    int e = blockIdx.x*blockDim.x + threadIdx.x;
    if (e >= Ee) return;
    int s = esrc(ei,e), d = edst(ei,e);
    if (!g_matched[s] && !g_matched[d]){
        int j = atomicAdd(&g_fcnt, 1);
        g_frontA[j] = e;
        g_best[s]=0ULL; g_best[d]=0ULL;
    }
}

__global__ __launch_bounds__(1024) void k_matchp(const void* __restrict__ ei){
    __shared__ int s_next;
    int t = threadIdx.x;
    int n = g_fcnt;
    int* cur = g_frontA;
    int* nxt = g_frontB;
    while (n > 0){
        for (int i=t;i<n;i+=1024){
            int e = cur[i];
            unsigned long long k = g_key[e];
            atomicMax(&g_best[esrc(ei,e)], k);
            atomicMax(&g_best[edst(ei,e)], k);
        }
        __syncthreads();
        for (int i=t;i<n;i+=1024){
            int e = cur[i];
            int s = esrc(ei,e), d = edst(ei,e);
            unsigned long long k = g_key[e];
            if (g_best[s]==k && g_best[d]==k) do_match(e,s,d);
        }
        __syncthreads();
        if (t==0) s_next = 0;
        __syncthreads();
        for (int i=t;i<n;i+=1024){
            int e = cur[i];
            int s = esrc(ei,e), d = edst(ei,e);
            if (!g_matched[s] && !g_matched[d]){
                int j = atomicAdd(&s_next, 1);
                nxt[j] = e;
                g_best[s]=0ULL; g_best[d]=0ULL;
            }
        }
        __syncthreads();
        n = s_next;
        int* tp = cur; cur = nxt; nxt = tp;
        __syncthreads();
    }
}

// ---------------- pooling (pairs/singletons only) ----------------
__global__ void k_xpool(const float* __restrict__ x){
    int idx = blockIdx.x*blockDim.x + threadIdx.x;
    if (idx >= Nn*64) return;
    int n = idx >> 6, c4 = (idx & 63) << 2;
    float4* o = (float4*)&g_xp[(size_t)n*256 + c4];
    if (g_cluster[n] != n){ *o = make_float4(0.f,0.f,0.f,0.f); return; }
    float ns = g_nscore[n];
    float4 v = *(const float4*)&x[(size_t)n*256 + c4];
    int p = g_partner[n];
    if (p >= 0){
        float4 u = *(const float4*)&x[(size_t)p*256 + c4];
        v.x+=u.x; v.y+=u.y; v.z+=u.z; v.w+=u.w;
    }
    v.x*=ns; v.y*=ns; v.z*=ns; v.w*=ns;
    *o = v;
}

// ---------------- contracted edge dedup (hash set) ----------------
__global__ void k_dedup(const void* __restrict__ ei){
    int e = blockIdx.x*blockDim.x + threadIdx.x;
    if (e >= Ee) return;
    int cs = g_cluster[esrc(ei,e)];
    int cd = g_cluster[edst(ei,e)];
    unsigned int key = (unsigned int)cs * (unsigned int)(Nn+1) + (unsigned int)cd;
    unsigned int h = ((key * 2654435761u) >> 10) & (HASHN - 1);
    while (true){
        unsigned int old = atomicCAS(&g_hash[h], 0xFFFFFFFFu, key);
        if (old == 0xFFFFFFFFu){
            int i = atomicAdd(&g_uc, 1);
            g_us[i] = cs; g_ud[i] = cd;
            break;
        }
        if (old == key) break;
        h = (h + 1) & (HASHN - 1);
    }
}

// ---------------- GEMM: C[32768,256] = A @ B[256,256] (+bias) ----------------
__global__ __launch_bounds__(256) void k_gemm(const float* __restrict__ A, const float* __restrict__ B,
                                              float* __restrict__ C, const float* __restrict__ bias){
    __shared__ __align__(16) float As[16][64];
    __shared__ __align__(16) float Bs[16][64];
    int bx = blockIdx.x, by = blockIdx.y;
    int t = threadIdx.x;
    int tx = t & 15, ty = t >> 4;
    int ar = t >> 2,  ac = (t & 3) << 2;
    int br = t >> 4,  bc = (t & 15) << 2;
    const float* Ab = A + (size_t)(by*64)*256;
    const float* Bb = B + bx*64;
    float acc[4][4] = {};
    for (int k0 = 0; k0 < 256; k0 += 16){
        float4 av = *(const float4*)(Ab + (size_t)ar*256 + k0 + ac);
        As[ac+0][ar]=av.x; As[ac+1][ar]=av.y; As[ac+2][ar]=av.z; As[ac+3][ar]=av.w;
        float4 bv = *(const float4*)(Bb + (size_t)(k0+br)*256 + bc);
        *(float4*)&Bs[br][bc] = bv;
        __syncthreads();
        #pragma unroll
        for (int kk=0; kk<16; kk++){
            float a[4], b[4];
            #pragma unroll
            for (int i=0;i<4;i++) a[i] = As[kk][ty*4+i];
            #pragma unroll
            for (int j=0;j<4;j++) b[j] = Bs[kk][tx*4+j];
            #pragma unroll
            for (int i=0;i<4;i++)
                #pragma unroll
                for (int j=0;j<4;j++) acc[i][j] += a[i]*b[j];
        }
        __syncthreads();
    }
    #pragma unroll
    for (int i=0;i<4;i++){
        int row = by*64 + ty*4 + i;
        int col = bx*64 + tx*4;
        float4 o = make_float4(acc[i][0],acc[i][1],acc[i][2],acc[i][3]);
        if (bias){ o.x+=bias[col]; o.y+=bias[col+1]; o.z+=bias[col+2]; o.w+=bias[col+3]; }
        *(float4*)(C + (size_t)row*256 + col) = o;
    }
}

// ---------------- GAT passes ----------------
__global__ void k_gatzero(float* __restrict__ out){
    int i = blockIdx.x*blockDim.x + threadIdx.x;
    out[i] = 0.f;
    if (i < Nn*4){ g_mx4[i]=0u; g_sum4[i]=0.f; }
}

__global__ __launch_bounds__(256) void k_gat_logit(const float* __restrict__ xl, const float* __restrict__ xr,
                                                   const float* __restrict__ att){
    int gt = blockIdx.x*blockDim.x + threadIdx.x;
    int e = gt >> 5, lane = gt & 31;
    if (e >= g_uc) return;
    int s = g_us[e], d = g_ud[e];
    int i0 = lane*8;
    float4 a0 = *(const float4*)(xl + (size_t)s*256 + i0);
    float4 a1 = *(const float4*)(xl + (size_t)s*256 + i0 + 4);
    float4 r0 = *(const float4*)(xr + (size_t)d*256 + i0);
    float4 r1 = *(const float4*)(xr + (size_t)d*256 + i0 + 4);
    float4 t0 = *(const float4*)(att + i0);
    float4 t1 = *(const float4*)(att + i0 + 4);
    float p = 0.f, h;
    h=a0.x+r0.x; p += (h>0.f?h:0.2f*h)*t0.x;
    h=a0.y+r0.y; p += (h>0.f?h:0.2f*h)*t0.y;
    h=a0.z+r0.z; p += (h>0.f?h:0.2f*h)*t0.z;
    h=a0.w+r0.w; p += (h>0.f?h:0.2f*h)*t0.w;
    h=a1.x+r1.x; p += (h>0.f?h:0.2f*h)*t1.x;
    h=a1.y+r1.y; p += (h>0.f?h:0.2f*h)*t1.y;
    h=a1.z+r1.z; p += (h>0.f?h:0.2f*h)*t1.z;
    h=a1.w+r1.w; p += (h>0.f?h:0.2f*h)*t1.w;
    p += __shfl_down_sync(0xffffffffu, p, 4, 8);
    p += __shfl_down_sync(0xffffffffu, p, 2, 8);
    p += __shfl_down_sync(0xffffffffu, p, 1, 8);
    if ((lane & 7) == 0){
        int hh = lane >> 3;
        g_logit[e*4+hh] = p;
        atomicMax(&g_mx4[d*4+hh], encf(p));
    }
}

__global__ void k_gat_exp(){
    int t = blockIdx.x*blockDim.x + threadIdx.x;
    int e = t >> 2;
    if (e >= g_uc) return;
    int d = g_ud[e], hh = t & 3;
    float ex = expf(g_logit[t] - decf(g_mx4[d*4+hh]));
    g_exv[t] = ex;
    atomicAdd(&g_sum4[d*4+hh], ex);
}

__global__ __launch_bounds__(256) void k_gat_out(const float* __restrict__ xl, float* __restrict__ out){
    int gt = blockIdx.x*blockDim.x + threadIdx.x;
    int e = gt >> 5, lane = gt & 31;
    if (e >= g_uc) return;
    int s = g_us[e], d = g_ud[e];
    int hh = lane >> 3;
    float alpha = g_exv[e*4+hh] / g_sum4[d*4+hh];
    int i0 = lane*8;
    float4 a0 = *(const float4*)(xl + (size_t)s*256 + i0);
    float4 a1 = *(const float4*)(xl + (size_t)s*256 + i0 + 4);
    float* ob = out + (size_t)d*256 + i0;
    atomicAdd(ob+0, a0.x*alpha); atomicAdd(ob+1, a0.y*alpha);
    atomicAdd(ob+2, a0.z*alpha); atomicAdd(ob+3, a0.w*alpha);
    atomicAdd(ob+4, a1.x*alpha); atomicAdd(ob+5, a1.y*alpha);
    atomicAdd(ob+6, a1.z*alpha); atomicAdd(ob+7, a1.w*alpha);
}

// ---------------- graph layernorm + gelu ----------------
__global__ __launch_bounds__(256) void k_lnred(const float* __restrict__ h){
    int gt = blockIdx.x*blockDim.x + threadIdx.x;
    int w = gt >> 5, lane = gt & 31;
    if (w >= Nn) return;
    if (g_cluster[w] != w) return;
    double s1=0.0, s2=0.0;
    #pragma unroll
    for (int k=0;k<8;k++){
        float v = h[(size_t)w*256 + lane + 32*k];
        s1 += (double)v; s2 += (double)v*(double)v;
    }
    #pragma unroll
    for (int o=16;o;o>>=1){
        s1 += __shfl_down_sync(0xffffffffu, s1, o);
        s2 += __shfl_down_sync(0xffffffffu, s2, o);
    }
    if (lane==0){ atomicAdd(&g_lnsum, s1); atomicAdd(&g_lnsq, s2); }
}

__global__ void k_lnfin(){
    double cnt = (double)(Nn - g_P) * 256.0;
    double mean = g_lnsum / cnt;
    double var = g_lnsq / cnt - mean*mean;
    if (var < 0.0) var = 0.0;
    g_mean = mean;
    g_inv = 1.0 / (sqrt(var) + 1e-5);
}

__global__ void k_lngelu(float* __restrict__ h, const float* __restrict__ w, const float* __restrict__ b){
    int i = blockIdx.x*blockDim.x + threadIdx.x;
    int c = i & 255;
    float v = (float)(((double)h[i] - g_mean) * g_inv) * w[c] + b[c];
    h[i] = v * normcdff(v);
}

// ---------------- output gather ----------------
__global__ void k_out(const float* __restrict__ xt, float* __restrict__ out){
    int i = blockIdx.x*blockDim.x + threadIdx.x;
    int n = i >> 6, c4 = (i & 63) << 2;
    int r = g_cluster[n];
    float inv = 1.f / g_nscore[r];
    float4 v = *(const float4*)(xt + (size_t)r*256 + c4);
    v.x*=inv; v.y*=inv; v.z*=inv; v.w*=inv;
    *(float4*)(out + (size_t)n*256 + c4) = v;
}

// ---------------- launch ----------------
extern "C" void kernel_launch(void* const* d_in, const int* in_sizes, int n_in,
                              void* d_out, int out_size){
    const float* x  = (const float*)d_in[0];
    const void*  ei = d_in[1];

    // Locate pool_w robustly: first input with exactly 512 elements.
    int o = -1;
    for (int i = 2; i < n_in; i++){
        if (in_sizes[i] == 512){ o = i; break; }
    }
    if (o < 0) o = 4; // fallback: assume canonical layout
    const float* pool_w = (const float*)d_in[o];
    const float* pool_b = (const float*)d_in[o+1];
    const float* w_l0   = (const float*)d_in[o+2];
    const float* w_r0   = (const float*)d_in[o+3];
    const float* att0   = (const float*)d_in[o+4];
    const float* w_l1   = (const float*)d_in[o+5];
    const float* w_r1   = (const float*)d_in[o+6];
    const float* att1   = (const float*)d_in[o+7];
    const float* ln_w0  = (const float*)d_in[o+8];
    const float* ln_b0  = (const float*)d_in[o+9];
    const float* ln_w1  = (const float*)d_in[o+10];
    const float* ln_b1  = (const float*)d_in[o+11];
    const float* lin_w  = (const float*)d_in[o+12];
    const float* lin_b  = (const float*)d_in[o+13];
    float*       out    = (float*)d_out;

    float *pxp, *pxl, *pxr, *ph;
    cudaGetSymbolAddress((void**)&pxp, g_xp);
    cudaGetSymbolAddress((void**)&pxl, g_xl);
    cudaGetSymbolAddress((void**)&pxr, g_xr);
    cudaGetSymbolAddress((void**)&ph,  g_h);

    // scores + matching + pooling + dedup
    k_detect<<<1, 1>>>(ei);
    k_init<<<(HASHN+255)/256, 256>>>();
    k_pool<<<Nn/8, 256>>>(x, pool_w);
    k_raw<<<Ee/256, 256>>>(ei, pool_b);
    k_ex<<<Ee/256, 256>>>(ei);
    k_scorekey<<<Ee/256, 256>>>(ei);
    k_max1<<<Ee/256, 256>>>(ei);
    k_match1<<<Ee/256, 256>>>(ei);
    k_compact1<<<Ee/256, 256>>>(ei);
    k_matchp<<<1, 1024>>>(ei);
    k_xpool<<<Nn/4, 256>>>(x);
    k_dedup<<<Ee/256, 256>>>(ei);

    dim3 gg(4, 512);
    // layer 1
    k_gemm<<<gg, 256>>>(pxp, w_l0, pxl, (const float*)nullptr);
    k_gemm<<<gg, 256>>>(pxp, w_r0, pxr, (const float*)nullptr);
    k_gatzero<<<Nn, 256>>>(ph);
    k_gat_logit<<<Ee/8, 256>>>(pxl, pxr, att0);
    k_gat_exp<<<Ee/64, 256>>>();
    k_gat_out<<<Ee/8, 256>>>(pxl, ph);
    k_lnzero<<<1,1>>>();
    k_lnred<<<Nn/8, 256>>>(ph);
    k_lnfin<<<1,1>>>();
    k_lngelu<<<Nn, 256>>>(ph, ln_w0, ln_b0);
    // layer 2
    k_gemm<<<gg, 256>>>(ph, w_l1, pxl, (const float*)nullptr);
    k_gemm<<<gg, 256>>>(ph, w_r1, pxr, (const float*)nullptr);
    k_gatzero<<<Nn, 256>>>(pxp);
    k_gat_logit<<<Ee/8, 256>>>(pxl, pxr, att1);
    k_gat_exp<<<Ee/64, 256>>>();
    k_gat_out<<<Ee/8, 256>>>(pxl, pxp);
    k_lnzero<<<1,1>>>();
    k_lnred<<<Nn/8, 256>>>(pxp);
    k_lnfin<<<1,1>>>();
    k_lngelu<<<Nn, 256>>>(pxp, ln_w1, ln_b1);
    // final linear + gather
    k_gemm<<<gg, 256>>>(pxp, lin_w, ph, lin_b);
    k_out<<<Nn/4, 256>>>(ph, out);
}

// round 11
// speedup vs baseline: 1.0014x; 1.0014x over previous
#include <cuda_runtime.h>
#include <math.h>

#define Nn 32768
#define Ee 262144
#define HASHN (1u<<20)

// ---------------- static device scratch ----------------
__device__ double g_a[Nn], g_b[Nn];
__device__ double g_rawex[Ee];
__device__ unsigned long long g_mx[Nn];
__device__ double g_sum[Nn];
__device__ float  g_score[Ee];
__device__ unsigned long long g_key[Ee];
__device__ unsigned long long g_best[Nn];
__device__ int    g_matched[Nn], g_cluster[Nn], g_partner[Nn];
__device__ float  g_nscore[Nn];
__device__ int    g_frontA[Ee], g_frontB[Ee];
__device__ int    g_fcnt, g_P, g_uc, g_e64;
__device__ unsigned int g_hash[HASHN];
__device__ int    g_us[Ee], g_ud[Ee];
__device__ float  g_logit[Ee*4], g_exv[Ee*4];
__device__ unsigned int g_mx4[Nn*4];
__device__ float  g_sum4[Nn*4];
__device__ double g_lnsum, g_lnsq, g_mean, g_inv;
__device__ float  g_xp[(size_t)Nn*256];
__device__ float  g_xl[(size_t)Nn*256];
__device__ float  g_xr[(size_t)Nn*256];
__device__ float  g_h [(size_t)Nn*256];

// ---------------- edge accessors (dtype-agnostic) ----------------
static __device__ __forceinline__ int esrc(const void* ei, int e){
    return g_e64 ? (int)((const long long*)ei)[e] : ((const int*)ei)[e];
}
static __device__ __forceinline__ int edst(const void* ei, int e){
    return g_e64 ? (int)((const long long*)ei)[Ee + e] : ((const int*)ei)[Ee + e];
}

// ---------------- order-preserving encodings ----------------
static __device__ __forceinline__ unsigned long long encd(double x){
    unsigned long long b = (unsigned long long)__double_as_longlong(x);
    return (b & 0x8000000000000000ULL) ? ~b : (b | 0x8000000000000000ULL);
}
static __device__ __forceinline__ double decd(unsigned long long u){
    unsigned long long b = (u & 0x8000000000000000ULL) ? (u ^ 0x8000000000000000ULL) : ~u;
    return __longlong_as_double((long long)b);
}
static __device__ __forceinline__ unsigned int encf(float x){
    unsigned int b = __float_as_uint(x);
    return (b & 0x80000000u) ? ~b : (b | 0x80000000u);
}
static __device__ __forceinline__ float decf(unsigned int u){
    unsigned int b = (u & 0x80000000u) ? (u ^ 0x80000000u) : ~u;
    return __uint_as_float(b);
}

// ---------------- dtype detect + init ----------------
__global__ void k_detect(const void* ei){
    const long long* p = (const long long*)ei;
    int ok = 1;
    for (int i = 0; i < 16; i++){
        long long v = p[i];
        if (v < 0 || v >= Nn) { ok = 0; break; }
    }
    g_e64 = ok;
}

__global__ void k_init(){
    int i = blockIdx.x*blockDim.x + threadIdx.x;
    if (i < (int)HASHN) g_hash[i] = 0xFFFFFFFFu;
    if (i < Nn){
        g_mx[i]=0ULL; g_sum[i]=0.0; g_best[i]=0ULL;
        g_matched[i]=0; g_cluster[i]=i; g_partner[i]=-1; g_nscore[i]=1.0f;
    }
    if (i == 0){ g_P=0; g_uc=0; g_fcnt=0; }
}
__global__ void k_lnzero(){ g_lnsum = 0.0; g_lnsq = 0.0; }

// ---------------- edge scores ----------------
__global__ __launch_bounds__(256) void k_pool(const float* __restrict__ x, const float* __restrict__ pw){
    int gt = blockIdx.x*blockDim.x + threadIdx.x;
    int w = gt >> 5, lane = gt & 31;
    if (w >= Nn) return;
    double sa=0.0, sb=0.0;
    #pragma unroll
    for (int k=0;k<8;k++){
        int c = lane + 32*k;
        double xv = (double)x[(size_t)w*256 + c];
        sa += xv * (double)__ldg(&pw[c]);
        sb += xv * (double)__ldg(&pw[256 + c]);
    }
    #pragma unroll
    for (int o=16;o;o>>=1){
        sa += __shfl_down_sync(0xffffffffu, sa, o);
        sb += __shfl_down_sync(0xffffffffu, sb, o);
    }
    if (lane==0){ g_a[w]=sa; g_b[w]=sb; }
}

__global__ void k_raw(const void* __restrict__ ei, const float* __restrict__ pb){
    int e = blockIdx.x*blockDim.x + threadIdx.x;
    if (e >= Ee) return;
    int s = esrc(ei,e), d = edst(ei,e);
    double r = g_a[s] + g_b[d] + (double)pb[0];
    g_rawex[e] = r;
    atomicMax(&g_mx[d], encd(r));
}

__global__ void k_ex(const void* __restrict__ ei){
    int e = blockIdx.x*blockDim.x + threadIdx.x;
    if (e >= Ee) return;
    int d = edst(ei,e);
    double ex = exp(g_rawex[e] - decd(g_mx[d]));
    g_rawex[e] = ex;
    atomicAdd(&g_sum[d], ex);
}

__global__ void k_scorekey(const void* __restrict__ ei){
    int e = blockIdx.x*blockDim.x + threadIdx.x;
    if (e >= Ee) return;
    int d = edst(ei,e);
    float fs = (float)(g_rawex[e]/g_sum[d] + 0.5);
    g_score[e] = fs;
    unsigned int ub = __float_as_uint(fs) | 0x80000000u;   // fs > 0 always
    g_key[e] = ((unsigned long long)ub << 32) | (unsigned long long)(0xFFFFFFFFu - (unsigned)e);
}

// ---------------- matching (locally-dominant == sequential greedy) ----------------
static __device__ __forceinline__ void do_match(int e, int s, int d){
    int rep = s<d ? s : d;
    int oth = s<d ? d : s;
    g_matched[s]=1; g_matched[d]=1;
    g_cluster[oth]=rep;
    g_partner[rep]=oth;
    g_nscore[rep]=g_score[e];
    atomicAdd(&g_P, 1);
}

__global__ void k_max1(const void* __restrict__ ei){
    int e = blockIdx.x*blockDim.x + threadIdx.x;
    if (e >= Ee) return;
    unsigned long long k = g_key[e];
    atomicMax(&g_best[esrc(ei,e)], k);
    atomicMax(&g_best[edst(ei,e)], k);
}
__global__ void k_match1(const void* __restrict__ ei){
    int e = blockIdx.x*blockDim.x + threadIdx.x;
    if (e >= Ee) return;
    int s = esrc(ei,e), d = edst(ei,e);
    unsigned long long k = g_key[e];
    if (g_best[s]==k && g_best[d]==k) do_match(e,s,d);
}
__global__ void k_compact1(const void* __restrict__ ei){
    int e = blockIdx.x*blockDim.x + threadIdx.x;
    if (e >= Ee) return;
    int s = esrc(ei,e), d = edst(ei,e);
    if (!g_matched[s] && !g_matched[d]){
        int j = atomicAdd(&g_fcnt, 1);
        g_frontA[j] = e;
        g_best[s]=0ULL; g_best[d]=0ULL;
    }
}

__global__ __launch_bounds__(1024) void k_matchp(const void* __restrict__ ei){
    __shared__ int s_next;
    int t = threadIdx.x;
    int n = g_fcnt;
    int* cur = g_frontA;
    int* nxt = g_frontB;
    while (n > 0){
        for (int i=t;i<n;i+=1024){
            int e = cur[i];
            unsigned long long k = g_key[e];
            atomicMax(&g_best[esrc(ei,e)], k);
            atomicMax(&g_best[edst(ei,e)], k);
        }
        __syncthreads();
        for (int i=t;i<n;i+=1024){
            int e = cur[i];
            int s = esrc(ei,e), d = edst(ei,e);
            unsigned long long k = g_key[e];
            if (g_best[s]==k && g_best[d]==k) do_match(e,s,d);
        }
        __syncthreads();
        if (t==0) s_next = 0;
        __syncthreads();
        for (int i=t;i<n;i+=1024){
            int e = cur[i];
            int s = esrc(ei,e), d = edst(ei,e);
            if (!g_matched[s] && !g_matched[d]){
                int j = atomicAdd(&s_next, 1);
                nxt[j] = e;
                g_best[s]=0ULL; g_best[d]=0ULL;
            }
        }
        __syncthreads();
        n = s_next;
        int* tp = cur; cur = nxt; nxt = tp;
        __syncthreads();
    }
}

// ---------------- pooling (pairs/singletons only) ----------------
__global__ void k_xpool(const float* __restrict__ x){
    int idx = blockIdx.x*blockDim.x + threadIdx.x;
    if (idx >= Nn*64) return;
    int n = idx >> 6, c4 = (idx & 63) << 2;
    float4* o = (float4*)&g_xp[(size_t)n*256 + c4];
    if (g_cluster[n] != n){ *o = make_float4(0.f,0.f,0.f,0.f); return; }
    float ns = g_nscore[n];
    float4 v = *(const float4*)&x[(size_t)n*256 + c4];
    int p = g_partner[n];
    if (p >= 0){
        float4 u = *(const float4*)&x[(size_t)p*256 + c4];
        v.x+=u.x; v.y+=u.y; v.z+=u.z; v.w+=u.w;
    }
    v.x*=ns; v.y*=ns; v.z*=ns; v.w*=ns;
    *o = v;
}

// ---------------- contracted edge dedup (hash set) ----------------
__global__ void k_dedup(const void* __restrict__ ei){
    int e = blockIdx.x*blockDim.x + threadIdx.x;
    if (e >= Ee) return;
    int cs = g_cluster[esrc(ei,e)];
    int cd = g_cluster[edst(ei,e)];
    unsigned int key = (unsigned int)cs * (unsigned int)(Nn+1) + (unsigned int)cd;
    unsigned int h = ((key * 2654435761u) >> 10) & (HASHN - 1);
    while (true){
        unsigned int old = atomicCAS(&g_hash[h], 0xFFFFFFFFu, key);
        if (old == 0xFFFFFFFFu){
            int i = atomicAdd(&g_uc, 1);
            g_us[i] = cs; g_ud[i] = cd;
            break;
        }
        if (old == key) break;
        h = (h + 1) & (HASHN - 1);
    }
}

// ---------------- GEMM: C[32768,256] = A @ B[256,256] (+bias) ----------------
__global__ __launch_bounds__(256) void k_gemm(const float* __restrict__ A, const float* __restrict__ B,
                                              float* __restrict__ C, const float* __restrict__ bias){
    __shared__ __align__(16) float As[16][64];
    __shared__ __align__(16) float Bs[16][64];
    int bx = blockIdx.x, by = blockIdx.y;
    int t = threadIdx.x;
    int tx = t & 15, ty = t >> 4;
    int ar = t >> 2,  ac = (t & 3) << 2;
    int br = t >> 4,  bc = (t & 15) << 2;
    const float* Ab = A + (size_t)(by*64)*256;
    const float* Bb = B + bx*64;
    float acc[4][4] = {};
    for (int k0 = 0; k0 < 256; k0 += 16){
        float4 av = *(const float4*)(Ab + (size_t)ar*256 + k0 + ac);
        As[ac+0][ar]=av.x; As[ac+1][ar]=av.y; As[ac+2][ar]=av.z; As[ac+3][ar]=av.w;
        float4 bv = *(const float4*)(Bb + (size_t)(k0+br)*256 + bc);
        *(float4*)&Bs[br][bc] = bv;
        __syncthreads();
        #pragma unroll
        for (int kk=0; kk<16; kk++){
            float a[4], b[4];
            #pragma unroll
            for (int i=0;i<4;i++) a[i] = As[kk][ty*4+i];
            #pragma unroll
            for (int j=0;j<4;j++) b[j] = Bs[kk][tx*4+j];
            #pragma unroll
            for (int i=0;i<4;i++)
                #pragma unroll
                for (int j=0;j<4;j++) acc[i][j] += a[i]*b[j];
        }
        __syncthreads();
    }
    #pragma unroll
    for (int i=0;i<4;i++){
        int row = by*64 + ty*4 + i;
        int col = bx*64 + tx*4;
        float4 o = make_float4(acc[i][0],acc[i][1],acc[i][2],acc[i][3]);
        if (bias){ o.x+=bias[col]; o.y+=bias[col+1]; o.z+=bias[col+2]; o.w+=bias[col+3]; }
        *(float4*)(C + (size_t)row*256 + col) = o;
    }
}

// ---------------- GAT passes ----------------
__global__ void k_gatzero(float* __restrict__ out){
    int i = blockIdx.x*blockDim.x + threadIdx.x;
    out[i] = 0.f;
    if (i < Nn*4){ g_mx4[i]=0u; g_sum4[i]=0.f; }
}

__global__ __launch_bounds__(256) void k_gat_logit(const float* __restrict__ xl, const float* __restrict__ xr,
                                                   const float* __restrict__ att){
    int gt = blockIdx.x*blockDim.x + threadIdx.x;
    int e = gt >> 5, lane = gt & 31;
    if (e >= g_uc) return;
    int s = g_us[e], d = g_ud[e];
    int i0 = lane*8;
    float4 a0 = *(const float4*)(xl + (size_t)s*256 + i0);
    float4 a1 = *(const float4*)(xl + (size_t)s*256 + i0 + 4);
    float4 r0 = *(const float4*)(xr + (size_t)d*256 + i0);
    float4 r1 = *(const float4*)(xr + (size_t)d*256 + i0 + 4);
    float4 t0 = *(const float4*)(att + i0);
    float4 t1 = *(const float4*)(att + i0 + 4);
    float p = 0.f, h;
    h=a0.x+r0.x; p += (h>0.f?h:0.2f*h)*t0.x;
    h=a0.y+r0.y; p += (h>0.f?h:0.2f*h)*t0.y;
    h=a0.z+r0.z; p += (h>0.f?h:0.2f*h)*t0.z;
    h=a0.w+r0.w; p += (h>0.f?h:0.2f*h)*t0.w;
    h=a1.x+r1.x; p += (h>0.f?h:0.2f*h)*t1.x;
    h=a1.y+r1.y; p += (h>0.f?h:0.2f*h)*t1.y;
    h=a1.z+r1.z; p += (h>0.f?h:0.2f*h)*t1.z;
    h=a1.w+r1.w; p += (h>0.f?h:0.2f*h)*t1.w;
    p += __shfl_down_sync(0xffffffffu, p, 4, 8);
    p += __shfl_down_sync(0xffffffffu, p, 2, 8);
    p += __shfl_down_sync(0xffffffffu, p, 1, 8);
    if ((lane & 7) == 0){
        int hh = lane >> 3;
        g_logit[e*4+hh] = p;
        atomicMax(&g_mx4[d*4+hh], encf(p));
    }
}

__global__ void k_gat_exp(){
    int t = blockIdx.x*blockDim.x + threadIdx.x;
    int e = t >> 2;
    if (e >= g_uc) return;
    int d = g_ud[e], hh = t & 3;
    float ex = expf(g_logit[t] - decf(g_mx4[d*4+hh]));
    g_exv[t] = ex;
    atomicAdd(&g_sum4[d*4+hh], ex);
}

__global__ __launch_bounds__(256) void k_gat_out(const float* __restrict__ xl, float* __restrict__ out){
    int gt = blockIdx.x*blockDim.x + threadIdx.x;
    int e = gt >> 5, lane = gt & 31;
    if (e >= g_uc) return;
    int s = g_us[e], d = g_ud[e];
    int hh = lane >> 3;
    float alpha = g_exv[e*4+hh] / g_sum4[d*4+hh];
    int i0 = lane*8;
    float4 a0 = *(const float4*)(xl + (size_t)s*256 + i0);
    float4 a1 = *(const float4*)(xl + (size_t)s*256 + i0 + 4);
    float* ob = out + (size_t)d*256 + i0;
    atomicAdd(ob+0, a0.x*alpha); atomicAdd(ob+1, a0.y*alpha);
    atomicAdd(ob+2, a0.z*alpha); atomicAdd(ob+3, a0.w*alpha);
    atomicAdd(ob+4, a1.x*alpha); atomicAdd(ob+5, a1.y*alpha);
    atomicAdd(ob+6, a1.z*alpha); atomicAdd(ob+7, a1.w*alpha);
}

// ---------------- graph layernorm + gelu ----------------
__global__ __launch_bounds__(256) void k_lnred(const float* __restrict__ h){
    int gt = blockIdx.x*blockDim.x + threadIdx.x;
    int w = gt >> 5, lane = gt & 31;
    if (w >= Nn) return;
    if (g_cluster[w] != w) return;
    double s1=0.0, s2=0.0;
    #pragma unroll
    for (int k=0;k<8;k++){
        float v = h[(size_t)w*256 + lane + 32*k];
        s1 += (double)v; s2 += (double)v*(double)v;
    }
    #pragma unroll
    for (int o=16;o;o>>=1){
        s1 += __shfl_down_sync(0xffffffffu, s1, o);
        s2 += __shfl_down_sync(0xffffffffu, s2, o);
    }
    if (lane==0){ atomicAdd(&g_lnsum, s1); atomicAdd(&g_lnsq, s2); }
}

__global__ void k_lnfin(){
    double cnt = (double)(Nn - g_P) * 256.0;
    double mean = g_lnsum / cnt;
    double var = g_lnsq / cnt - mean*mean;
    if (var < 0.0) var = 0.0;
    g_mean = mean;
    g_inv = 1.0 / (sqrt(var) + 1e-5);
}

__global__ void k_lngelu(float* __restrict__ h, const float* __restrict__ w, const float* __restrict__ b){
    int i = blockIdx.x*blockDim.x + threadIdx.x;
    int c = i & 255;
    float v = (float)(((double)h[i] - g_mean) * g_inv) * w[c] + b[c];
    h[i] = v * normcdff(v);
}

// ---------------- output gather ----------------
__global__ void k_out(const float* __restrict__ xt, float* __restrict__ out){
    int i = blockIdx.x*blockDim.x + threadIdx.x;
    int n = i >> 6, c4 = (i & 63) << 2;
    int r = g_cluster[n];
    float inv = 1.f / g_nscore[r];
    float4 v = *(const float4*)(xt + (size_t)r*256 + c4);
    v.x*=inv; v.y*=inv; v.z*=inv; v.w*=inv;
    *(float4*)(out + (size_t)n*256 + c4) = v;
}

// ---------------- launch ----------------
extern "C" void kernel_launch(void* const* d_in, const int* in_sizes, int n_in,
                              void* d_out, int out_size){
    const float* x  = (const float*)d_in[0];
    const void*  ei = d_in[1];

    // Locate pool_w robustly: first input with exactly 512 elements.
    int o = -1;
    for (int i = 2; i < n_in; i++){
        if (in_sizes[i] == 512){ o = i; break; }
    }
    if (o < 0) o = 4; // fallback: assume canonical layout
    const float* pool_w = (const float*)d_in[o];
    const float* pool_b = (const float*)d_in[o+1];
    const float* w_l0   = (const float*)d_in[o+2];
    const float* w_r0   = (const float*)d_in[o+3];
    const float* att0   = (const float*)d_in[o+4];
    const float* w_l1   = (const float*)d_in[o+5];
    const float* w_r1   = (const float*)d_in[o+6];
    const float* att1   = (const float*)d_in[o+7];
    const float* ln_w0  = (const float*)d_in[o+8];
    const float* ln_b0  = (const float*)d_in[o+9];
    const float* ln_w1  = (const float*)d_in[o+10];
    const float* ln_b1  = (const float*)d_in[o+11];
    const float* lin_w  = (const float*)d_in[o+12];
    const float* lin_b  = (const float*)d_in[o+13];
    float*       out    = (float*)d_out;

    float *pxp, *pxl, *pxr, *ph;
    cudaGetSymbolAddress((void**)&pxp, g_xp);
    cudaGetSymbolAddress((void**)&pxl, g_xl);
    cudaGetSymbolAddress((void**)&pxr, g_xr);
    cudaGetSymbolAddress((void**)&ph,  g_h);

    // scores + matching + pooling + dedup
    k_detect<<<1, 1>>>(ei);
    k_init<<<(HASHN+255)/256, 256>>>();
    k_pool<<<Nn/8, 256>>>(x, pool_w);
    k_raw<<<Ee/256, 256>>>(ei, pool_b);
    k_ex<<<Ee/256, 256>>>(ei);
    k_scorekey<<<Ee/256, 256>>>(ei);
    k_max1<<<Ee/256, 256>>>(ei);
    k_match1<<<Ee/256, 256>>>(ei);
    k_compact1<<<Ee/256, 256>>>(ei);
    k_matchp<<<1, 1024>>>(ei);
    k_xpool<<<Nn/4, 256>>>(x);
    k_dedup<<<Ee/256, 256>>>(ei);

    dim3 gg(4, 512);
    // layer 1
    k_gemm<<<gg, 256>>>(pxp, w_l0, pxl, (const float*)nullptr);
    k_gemm<<<gg, 256>>>(pxp, w_r0, pxr, (const float*)nullptr);
    k_gatzero<<<Nn, 256>>>(ph);
    k_gat_logit<<<Ee/8, 256>>>(pxl, pxr, att0);
    k_gat_exp<<<Ee/64, 256>>>();
    k_gat_out<<<Ee/8, 256>>>(pxl, ph);
    k_lnzero<<<1,1>>>();
    k_lnred<<<Nn/8, 256>>>(ph);
    k_lnfin<<<1,1>>>();
    k_lngelu<<<Nn, 256>>>(ph, ln_w0, ln_b0);
    // layer 2
    k_gemm<<<gg, 256>>>(ph, w_l1, pxl, (const float*)nullptr);
    k_gemm<<<gg, 256>>>(ph, w_r1, pxr, (const float*)nullptr);
    k_gatzero<<<Nn, 256>>>(pxp);
    k_gat_logit<<<Ee/8, 256>>>(pxl, pxr, att1);
    k_gat_exp<<<Ee/64, 256>>>();
    k_gat_out<<<Ee/8, 256>>>(pxl, pxp);
    k_lnzero<<<1,1>>>();
    k_lnred<<<Nn/8, 256>>>(pxp);
    k_lnfin<<<1,1>>>();
    k_lngelu<<<Nn, 256>>>(pxp, ln_w1, ln_b1);
    // final linear + gather
    k_gemm<<<gg, 256>>>(pxp, lin_w, ph, lin_b);
    k_out<<<Nn/4, 256>>>(ph, out);
}